// round 16
// baseline (speedup 1.0000x reference)
#include <cuda_runtime.h>
#include <cuda_bf16.h>
#include <math.h>
#include <stdint.h>

// ---------------- problem constants ----------------
#define NHEAD   4
#define DHEAD   192
#define DMODEL  768
#define CIN     512
#define TLEN    1024
#define BATCH   32
#define NPATCH  253
#define NROW    (BATCH*NPATCH)     // 8096
#define KIN     (14*512)           // 7168
#define EPSF    1e-5f
#define NCLS    41

// ---------------- device scratch (no allocations allowed) ----------------
__device__ float g_x1[(size_t)BATCH*TLEN*CIN];
__device__ float g_x [(size_t)NROW*DMODEL];
__device__ float g_xin[(size_t)NROW*DMODEL];
__device__ float g_xc [(size_t)NROW*DMODEL];
__device__ float g_gates[(size_t)NROW*4*DMODEL];   // [b*253+s][g][h][e]
__device__ float g_gt[(size_t)NROW*4*DMODEL];      // [s][g*4+h][e][b]
__device__ float g_y [(size_t)NROW*DMODEL];        // [s][h][e][b]
__device__ float g_Rv[(size_t)5*NHEAD*DHEAD*DHEAD*4]; // [l][h][d][e][g]
__device__ float g_h2[2][NHEAD][2][DHEAD][16];     // [buf][h][bhalf][d][b16]
__device__ unsigned g_ctr2[NHEAD*2];

// ---------------- tf32 helpers ----------------
__device__ __forceinline__ uint32_t f2tf32(float v) {
    uint32_t r;
    asm("cvt.rna.tf32.f32 %0, %1;" : "=r"(r) : "f"(v));
    return r;
}
__device__ __forceinline__ void tf32_split(float v, uint32_t& hi, uint32_t& lo) {
    hi = f2tf32(v);
    lo = f2tf32(v - __uint_as_float(hi));
}
__device__ __forceinline__ void mma_tf32(float4& d, const uint32_t a[4], const uint32_t b[2]) {
    asm volatile(
        "mma.sync.aligned.m16n8k8.row.col.f32.tf32.tf32.f32 "
        "{%0,%1,%2,%3},{%4,%5,%6,%7},{%8,%9},{%0,%1,%2,%3};"
        : "+f"(d.x), "+f"(d.y), "+f"(d.z), "+f"(d.w)
        : "r"(a[0]), "r"(a[1]), "r"(a[2]), "r"(a[3]),
          "r"(b[0]), "r"(b[1]));
}
__device__ __forceinline__ int bsw(int block) { return block ^ ((block >> 3) & 7); }

// release/acquire counter ops
__device__ __forceinline__ void red_release_add(unsigned* p, unsigned v) {
    asm volatile("red.release.gpu.global.add.u32 [%0], %1;" :: "l"(p), "r"(v) : "memory");
}
__device__ __forceinline__ unsigned ld_acquire(const unsigned* p) {
    unsigned v;
    asm volatile("ld.acquire.gpu.global.u32 %0, [%1];" : "=r"(v) : "l"(p) : "memory");
    return v;
}

// =====================================================================
// tf32 tensor-core GEMM. X3=true: tf32x3 (day/in_proj, 2 blk/SM);
// X3=false: single tf32 (gate GEMMs) — Asl elided (-8KB SMEM), 3 blk/SM.
// =====================================================================
template<int MODE, bool X3>
__global__ void __launch_bounds__(256, (MODE==2 ? 3 : 2)) gemm4(
    const float* __restrict__ Aext, const float* __restrict__ Bw,
    const float* __restrict__ bias, const int* __restrict__ day_idx, int layer)
{
    constexpr int M   = (MODE==0) ? (BATCH*TLEN) : NROW;
    constexpr int N   = (MODE==0) ? CIN : (MODE==1 ? DMODEL : DHEAD);
    constexpr int K   = (MODE==0) ? CIN : (MODE==1 ? KIN : DHEAD);
    constexpr int BN  = (MODE==2) ? 64 : 128;
    constexpr int LDC = (MODE==0) ? CIN : (MODE==1 ? DMODEL : 3072);
    constexpr int NT  = K / 8;
    constexpr int NTILE = (BN/2) / 8;
    constexpr int NTB   = BN / 8;
    constexpr int ASLN  = X3 ? (8*32*4) : 1;   // dead when !X3

    __shared__ __align__(16) uint32_t Ash[2][8*32*4];
    __shared__ __align__(16) uint32_t Asl[2][ASLN];
    __shared__ __align__(16) uint32_t Bsp[2][NTB*32*4];

    const int tid  = threadIdx.x;
    const int wid  = tid >> 5;
    const int lane = tid & 31;
    const int grp  = lane >> 2;
    const int tg   = lane & 3;

    const int rowbase = blockIdx.y * 128;
    const int colbase = blockIdx.x * BN;

    const float* bvec;
    float* Cbase;
    const float* aload;
    const float* bload;

    const int am  = tid >> 1;
    const int akq = (tid & 1) * 4;
    int mg0 = rowbase + am; if (mg0 > M - 1) mg0 = M - 1;

    if constexpr (MODE == 0) {
        const int day = day_idx[0];
        const float* Bbase = Bw + (size_t)day * K * N;
        bvec  = bias + (size_t)day * N;
        Cbase = g_x1;
        aload = Aext + (size_t)mg0 * K;
        bload = Bbase + (size_t)(tid >> 5) * N + colbase + (tid & 31) * 4;
    } else if constexpr (MODE == 1) {
        bvec  = bias;
        Cbase = g_x;
        int bb = mg0 / 253, p = mg0 - bb * 253;
        aload = g_x1 + ((size_t)bb * TLEN + (size_t)p * 4) * CIN;
        bload = Bw + (size_t)(colbase + (tid >> 1)) * KIN + (tid & 1) * 4;
    } else {
        const int z  = blockIdx.z;
        const int gg = z >> 2;
        const int hh = z & 3;
        const float* A = (gg < 2 ? g_xc : g_xin);
        const float* Bbase = Bw + (size_t)((layer*4 + gg)*4 + hh) * (192*192);
        bvec  = bias + (size_t)((layer*4 + hh)*4 + gg) * 192;
        Cbase = g_gates + (size_t)gg * 768 + (size_t)hh * 192;
        aload = A + (size_t)mg0 * DMODEL + hh * 192;
        bload = Bbase + (size_t)(tid >> 5) * 192 + colbase + (tid & 31) * 2;
    }

    float4 av, bv;
    auto fetchAB = [&](int t) {
        if constexpr (MODE == 1) {
            int kg = t*8 + akq;
            av = *reinterpret_cast<const float4*>(aload + (kg >> 9) * CIN + (kg & 511));
            bv = *reinterpret_cast<const float4*>(bload + t * 8);
        } else if constexpr (MODE == 0) {
            av = *reinterpret_cast<const float4*>(aload + t*8 + akq);
            bv = *reinterpret_cast<const float4*>(bload + (size_t)t * 8 * N);
        } else {
            av = *reinterpret_cast<const float4*>(aload + t*8 + akq);
            float2 v = *reinterpret_cast<const float2*>(bload + (size_t)t * 8 * 192);
            bv.x = v.x; bv.y = v.y; bv.z = 0.f; bv.w = 0.f;
        }
    };

    auto stage = [&](int buf) {
        {
            const float a4[4] = {av.x, av.y, av.z, av.w};
            const int mt  = am >> 4;
            const int r   = am & 15;
            const int g8  = r & 7;
            const int rhi = r >> 3;
            const int khi = akq >> 2;
            const int regj = rhi + 2*khi;
            #pragma unroll
            for (int j = 0; j < 4; j++) {
                int w = bsw(mt*32 + g8*4 + j) * 4 + regj;
                if constexpr (X3) {
                    uint32_t hi, lo; tf32_split(a4[j], hi, lo);
                    Ash[buf][w] = hi; Asl[buf][w] = lo;
                } else {
                    Ash[buf][w] = f2tf32(a4[j]);
                }
            }
        }
        if constexpr (MODE == 0) {
            const float b4[4] = {bv.x, bv.y, bv.z, bv.w};
            const int bk = tid >> 5, bn0 = (tid & 31) * 4;
            const int btg = bk & 3, bkhi = bk >> 2;
            #pragma unroll
            for (int j = 0; j < 4; j++) {
                int n = bn0 + j;
                int w = bsw((n >> 3)*32 + (n & 7)*4 + btg) * 4;
                uint32_t hi, lo; tf32_split(b4[j], hi, lo);
                Bsp[buf][w + bkhi] = hi; Bsp[buf][w + 2 + bkhi] = lo;
            }
        } else if constexpr (MODE == 1) {
            const float b4[4] = {bv.x, bv.y, bv.z, bv.w};
            const int bn = tid >> 1, bkhi = (tid & 1);
            #pragma unroll
            for (int j = 0; j < 4; j++) {
                int w = bsw((bn >> 3)*32 + (bn & 7)*4 + j) * 4;
                uint32_t hi, lo; tf32_split(b4[j], hi, lo);
                Bsp[buf][w + bkhi] = hi; Bsp[buf][w + 2 + bkhi] = lo;
            }
        } else {
            const int bk = tid >> 5, bn0 = (tid & 31) * 2;
            const int btg = bk & 3, bkhi = bk >> 2;
            const float b2[2] = {bv.x, bv.y};
            #pragma unroll
            for (int j = 0; j < 2; j++) {
                int n = bn0 + j;
                int w = bsw((n >> 3)*32 + (n & 7)*4 + btg) * 4;
                if constexpr (X3) {
                    uint32_t hi, lo; tf32_split(b2[j], hi, lo);
                    Bsp[buf][w + bkhi] = hi; Bsp[buf][w + 2 + bkhi] = lo;
                } else {
                    Bsp[buf][w + bkhi] = f2tf32(b2[j]);
                }
            }
        }
    };

    fetchAB(0);
    stage(0);
    __syncthreads();

    float4 acc[2][NTILE];
    #pragma unroll
    for (int mt = 0; mt < 2; mt++)
        #pragma unroll
        for (int nt = 0; nt < NTILE; nt++)
            acc[mt][nt] = make_float4(0.f, 0.f, 0.f, 0.f);

    for (int t = 0; t < NT; t++) {
        const int buf = t & 1;
        if (t + 1 < NT) fetchAB(t + 1);

        uint32_t ah[2][4], al[2][4];
        #pragma unroll
        for (int mtl = 0; mtl < 2; mtl++) {
            int mt = (wid & 3)*2 + mtl;
            int w = bsw(mt*32 + lane) * 4;
            *reinterpret_cast<uint4*>(ah[mtl]) = *reinterpret_cast<const uint4*>(&Ash[buf][w]);
            if constexpr (X3)
                *reinterpret_cast<uint4*>(al[mtl]) = *reinterpret_cast<const uint4*>(&Asl[buf][w]);
        }
        #pragma unroll
        for (int nt = 0; nt < NTILE; nt++) {
            int ntg = (wid >> 2)*NTILE + nt;
            uint4 bq = *reinterpret_cast<const uint4*>(&Bsp[buf][bsw(ntg*32 + lane) * 4]);
            uint32_t bh[2] = {bq.x, bq.y};
            uint32_t bl[2] = {bq.z, bq.w};
            #pragma unroll
            for (int mtl = 0; mtl < 2; mtl++) {
                if constexpr (X3) {
                    mma_tf32(acc[mtl][nt], al[mtl], bh);
                    mma_tf32(acc[mtl][nt], ah[mtl], bl);
                }
                mma_tf32(acc[mtl][nt], ah[mtl], bh);
            }
        }
        if (t + 1 < NT) { stage(buf ^ 1); __syncthreads(); }
    }

    #pragma unroll
    for (int mtl = 0; mtl < 2; mtl++) {
        int r0 = rowbase + (wid & 3)*32 + mtl*16 + grp;
        #pragma unroll
        for (int nt = 0; nt < NTILE; nt++) {
            int cc = colbase + (wid >> 2)*(BN/2) + nt*8 + tg*2;
            float2 bb = *reinterpret_cast<const float2*>(&bvec[cc]);
            if (r0 < M) {
                float2 v; v.x = acc[mtl][nt].x + bb.x; v.y = acc[mtl][nt].y + bb.y;
                if constexpr (MODE == 0) {
                    v.x = v.x/(1.f+fabsf(v.x)); v.y = v.y/(1.f+fabsf(v.y));
                }
                *reinterpret_cast<float2*>(Cbase + (size_t)r0 * LDC + cc) = v;
            }
            if (r0 + 8 < M) {
                float2 v; v.x = acc[mtl][nt].z + bb.x; v.y = acc[mtl][nt].w + bb.y;
                if constexpr (MODE == 0) {
                    v.x = v.x/(1.f+fabsf(v.x)); v.y = v.y/(1.f+fabsf(v.y));
                }
                *reinterpret_cast<float2*>(Cbase + (size_t)(r0+8) * LDC + cc) = v;
            }
        }
    }
}

// =====================================================================
// Re-layout rec_W [l][h][d][g][e] -> g_Rv [l][h][d][e][g]
// =====================================================================
__global__ void __launch_bounds__(256) transpose_Rv_kernel(
    const float* __restrict__ R, int lh0)
{
    int idx = blockIdx.x * 256 + threadIdx.x;
    int e = idx % 192;
    int t = idx / 192;
    int d = t % 192;
    int lh = lh0 + t / 192;
    const float* src = R + ((size_t)(lh*192 + d) * 4) * 192 + e;
    float4 v;
    v.x = src[0]; v.y = src[192]; v.z = src[384]; v.w = src[576];
    *reinterpret_cast<float4*>(g_Rv + ((size_t)(lh*192 + d) * 192 + e) * 4) = v;
}

// =====================================================================
// Transpose gates [b*253+s][g][h][e] -> g_gt [s][g*4+h][e][b]
// =====================================================================
__global__ void __launch_bounds__(256) transpose_gates_kernel()
{
    __shared__ float t[32][33];
    const int e0 = blockIdx.x * 32;
    const int s  = blockIdx.y;
    const int gh = blockIdx.z;          // g*4+h
    const int tx = threadIdx.x, ty = threadIdx.y;
    #pragma unroll
    for (int k = 0; k < 4; k++) {
        int b = ty + 8*k;
        t[b][tx] = g_gates[(size_t)(b*NPATCH + s) * 3072 + gh*192 + e0 + tx];
    }
    __syncthreads();
    #pragma unroll
    for (int k = 0; k < 4; k++) {
        int e = ty + 8*k;
        g_gt[((size_t)(s*16 + gh)*192 + e0 + e)*32 + tx] = t[tx][e];
    }
}

// =====================================================================
// scan init: zero 8 barrier counters
// =====================================================================
__global__ void scan_init_kernel()
{
    if (threadIdx.x < NHEAD*2) g_ctr2[threadIdx.x] = 0u;
}

// =====================================================================
// sLSTM scan v7c: scan7b + double-buffered hsm (removes post-spin sync)
// + all-thread acquire polling (removes BAR-parked wake).
// 256 blocks = 4h x 2bh x 32 e-slices(6e); 384 thr = 3 epair x 4 dh x 32.
// =====================================================================
__global__ void __launch_bounds__(384) scan7c_kernel(int layer, int nsteps)
{
    const int h  = blockIdx.x >> 6;
    const int bh = (blockIdx.x >> 5) & 1;
    const int j  = blockIdx.x & 31;
    const int e0 = j * 6;
    const int tid  = threadIdx.x;
    const int lane = tid & 31;
    const int w    = tid >> 5;          // 0..11
    const int epair = w >> 2;           // 0..2
    const int dh    = w & 3;            // 0..3
    const int eh    = lane >> 4;        // 0..1
    const int b     = lane & 15;        // 0..15
    const int eloc  = epair*2 + eh;     // 0..5
    const int e     = e0 + eloc;
    const int b32   = bh*16 + b;
    unsigned* ctr = &g_ctr2[h*2 + bh];

    __shared__ float4 Rs[192][6];       // 18.4 KB
    __shared__ float  hsm[2][192*16];   // 24 KB (double-buffered)
    __shared__ float4 part[3][6][16];   // 4.6 KB          => 47 KB total

    // load R slice once
    {
        const float4* src = reinterpret_cast<const float4*>(g_Rv)
                          + (size_t)(layer*4 + h) * 192 * 192;
        for (int i = tid; i < 192*6; i += 384) {
            int d = i / 6, el = i - d*6;
            Rs[d][el] = src[(size_t)d * 192 + e0 + el];
        }
    }
    float c = 0.f, n = 0.f, m = 0.f;
    const float* gtb = g_gt + ((size_t)h*192 + e)*32 + b32;   // + s*98304, g*24576
    float* ytb = g_y + ((size_t)h*192 + e)*32 + b32;          // + s*24576

    float pgi = 0.f, pgf = 0.f, pgz = 0.f, pgo = 0.f;
    if (dh == 0) {
        pgi = __ldg(gtb);
        pgf = __ldg(gtb + 24576);
        pgz = __ldg(gtb + 49152);
        pgo = __ldg(gtb + 73728);
    }
    __syncthreads();

    for (int s = 0; s < nsteps; s++) {
        const int p = s & 1;
        float a0=0.f, a1=0.f, a2=0.f, a3=0.f;
        if (s > 0) {
            // stage this half's h slab into hsm[p] (alternating buffers)
            const float4* hp = reinterpret_cast<const float4*>(&g_h2[p][h][bh][0][0]);
            #pragma unroll
            for (int i = 0; i < 2; i++) {
                int idx = tid + i * 384;            // 0..767
                float4 v = __ldcg(hp + idx);
                *reinterpret_cast<float4*>(&hsm[p][idx * 4]) = v;
            }
            __syncthreads();                        // staging visible

            const int d0 = dh * 48;
            #pragma unroll 4
            for (int d = d0; d < d0 + 48; d++) {
                float hv = hsm[p][d*16 + b];
                float4 r = Rs[d][eloc];
                a0 = fmaf(hv, r.x, a0);
                a1 = fmaf(hv, r.y, a1);
                a2 = fmaf(hv, r.z, a2);
                a3 = fmaf(hv, r.w, a3);
            }
        }
        if (dh > 0) part[dh-1][eloc][b] = make_float4(a0, a1, a2, a3);
        __syncthreads();                            // partials visible

        float y = 0.f;
        if (dh == 0) {
            #pragma unroll
            for (int k = 0; k < 3; k++) {
                float4 q = part[k][eloc][b];
                a0 += q.x; a1 += q.y; a2 += q.z; a3 += q.w;
            }
            float iraw = a0 + pgi;
            float fraw = a1 + pgf;
            float zraw = a2 + pgz;
            float oraw = a3 + pgo;
            float lsf  = fminf(fraw, 0.f) - __logf(1.f + __expf(-fabsf(fraw)));
            float lfm  = m + lsf;
            float mnew = (s == 0) ? iraw : fmaxf(iraw, lfm);
            float ig = __expf(iraw - mnew), fg = __expf(lfm - mnew);
            float t2 = __expf(-2.f * fabsf(zraw));
            float th = copysignf(__fdividef(1.f - t2, 1.f + t2), zraw);
            float cnew = fg * c + ig * th;
            float nnew = fg * n + ig;
            float sg = __fdividef(1.f, 1.f + __expf(-oraw));
            y  = __fdividef(cnew, nnew) * sg;
            c = cnew; n = nnew; m = mnew;
            if (s + 1 < nsteps) g_h2[p ^ 1][h][bh][e][b] = y;
        }

        if (s + 1 < nsteps) {
            __syncthreads();                        // h stores done block-wide
            if (tid == 0) red_release_add(ctr, 1u); // release
            if (dh == 0) {                          // overlap with spin window
                ytb[(size_t)s * 24576] = y;
                const float* gp = gtb + (size_t)(s + 1) * 98304;
                pgi = __ldg(gp);
                pgf = __ldg(gp + 24576);
                pgz = __ldg(gp + 49152);
                pgo = __ldg(gp + 73728);
            }
            // ALL threads poll (no trailing __syncthreads: hsm double-buffered,
            // each thread's acquire orders its subsequent staging loads)
            const unsigned tgt = 32u * (unsigned)(s + 1);
            while (ld_acquire(ctr) < tgt) { }
        } else {
            if (dh == 0) ytb[(size_t)s * 24576] = y;
        }
    }
}

// =====================================================================
// LayerNorm (weight only): g_x -> g_xin.
// =====================================================================
__global__ void __launch_bounds__(256) ln_kernel(const float* __restrict__ w)
{
    __shared__ float sbuf[16];
    const int row = blockIdx.x;
    const int tid = threadIdx.x;
    const float* xp = g_x + (size_t)row * DMODEL;
    float v0 = xp[tid], v1 = xp[tid+256], v2 = xp[tid+512];
    float s  = v0 + v1 + v2;
    float ss = v0*v0 + v1*v1 + v2*v2;
    const unsigned full = 0xffffffffu;
    #pragma unroll
    for (int o = 16; o > 0; o >>= 1) {
        s  += __shfl_down_sync(full, s, o);
        ss += __shfl_down_sync(full, ss, o);
    }
    int wp = tid >> 5;
    if ((tid & 31) == 0) { sbuf[wp] = s; sbuf[wp+8] = ss; }
    __syncthreads();
    if (tid == 0) {
        float sa = 0.f, sb = 0.f;
        #pragma unroll
        for (int i = 0; i < 8; i++) { sa += sbuf[i]; sb += sbuf[i+8]; }
        sbuf[0] = sa; sbuf[8] = sb;
    }
    __syncthreads();
    float mu  = sbuf[0] * (1.f/768.f);
    float var = sbuf[8] * (1.f/768.f) - mu*mu;
    float rs  = rsqrtf(var + EPSF);
    float* op = g_xin + (size_t)row * DMODEL;
    op[tid]     = (v0 - mu) * rs * w[tid];
    op[tid+256] = (v1 - mu) * rs * w[tid+256];
    op[tid+512] = (v2 - mu) * rs * w[tid+512];
}

// =====================================================================
// Causal depthwise conv (k=4) + SiLU, chunked over time.
// =====================================================================
__global__ void __launch_bounds__(256) conv_kernel(
    const float* __restrict__ Wc, const float* __restrict__ cb)
{
    const int gid = blockIdx.x * 256 + threadIdx.x;
    const int d  = gid % DMODEL;
    const int r  = gid / DMODEL;
    const int ch = r & 3;
    const int b  = r >> 2;
    const int p0 = ch * 64;
    const int p1 = (p0 + 64 < NPATCH) ? p0 + 64 : NPATCH;
    const float w0 = Wc[d*4+0], w1 = Wc[d*4+1], w2 = Wc[d*4+2], w3 = Wc[d*4+3];
    const float bias = cb[d];
    const float* src = g_xin + (size_t)b * NPATCH * DMODEL + d;
    float*       dst = g_xc  + (size_t)b * NPATCH * DMODEL + d;
    float h0 = (p0 >= 3) ? src[(size_t)(p0-3)*DMODEL] : 0.f;
    float h1 = (p0 >= 2) ? src[(size_t)(p0-2)*DMODEL] : 0.f;
    float h2 = (p0 >= 1) ? src[(size_t)(p0-1)*DMODEL] : 0.f;
    for (int p = p0; p < p1; p++) {
        float v = src[(size_t)p * DMODEL];
        float o = fmaf(w0,h0, fmaf(w1,h1, fmaf(w2,h2, fmaf(w3,v, bias))));
        dst[(size_t)p * DMODEL] = o / (1.f + expf(-o));
        h0 = h1; h1 = h2; h2 = v;
    }
}

// =====================================================================
// GroupNorm + residual add into g_x (reads y from [s][h][e][b]).
// =====================================================================
__global__ void __launch_bounds__(128) gn_kernel(const float* __restrict__ gw)
{
    const int row  = blockIdx.x;          // m = b*253+s
    const int bb   = row / NPATCH;
    const int s    = row - bb * NPATCH;
    const int wp   = threadIdx.x >> 5;    // head
    const int lane = threadIdx.x & 31;
    const float* yb = g_y + ((size_t)(s*4 + wp) * 192) * 32 + bb;
    float v[6]; float sm = 0.f, ss = 0.f;
    #pragma unroll
    for (int j = 0; j < 6; j++) {
        v[j] = __ldg(yb + (size_t)(lane + 32*j) * 32);
        sm += v[j]; ss += v[j]*v[j];
    }
    const unsigned full = 0xffffffffu;
    #pragma unroll
    for (int o = 16; o > 0; o >>= 1) {
        sm += __shfl_xor_sync(full, sm, o);
        ss += __shfl_xor_sync(full, ss, o);
    }
    float mu  = sm * (1.f/192.f);
    float var = ss * (1.f/192.f) - mu*mu;
    float rs  = rsqrtf(var + EPSF);
    float* xp = g_x + (size_t)row * DMODEL + wp * 192;
    const float* gwp = gw + wp * 192;
    #pragma unroll
    for (int j = 0; j < 6; j++) {
        int i = lane + 32*j;
        xp[i] += (v[j] - mu) * rs * gwp[i];
    }
}

// =====================================================================
// Classifier — coalesced float4 W loads + shfl reduction.
// =====================================================================
__global__ void __launch_bounds__(256) out_kernel(
    const float* __restrict__ W, const float* __restrict__ bias,
    float* __restrict__ out)
{
    __shared__ float4 xs[192];
    const int row  = blockIdx.x;
    const int tid  = threadIdx.x;
    const int lane = tid & 31;
    const int wid  = tid >> 5;
    const float4* xp = reinterpret_cast<const float4*>(g_xin + (size_t)row * DMODEL);
    if (tid < 192) xs[tid] = xp[tid];
    __syncthreads();
    for (int cc = wid; cc < NCLS; cc += 8) {
        const float4* wr = reinterpret_cast<const float4*>(W + (size_t)cc * DMODEL);
        float acc = 0.f;
        #pragma unroll
        for (int i = 0; i < 6; i++) {
            float4 w4 = wr[lane + 32*i];
            float4 x4 = xs[lane + 32*i];
            acc += w4.x*x4.x + w4.y*x4.y + w4.z*x4.z + w4.w*x4.w;
        }
        #pragma unroll
        for (int o = 16; o > 0; o >>= 1)
            acc += __shfl_down_sync(0xffffffffu, acc, o);
        if (lane == 0) out[(size_t)row * NCLS + cc] = acc + bias[cc];
    }
}

// =====================================================================
// Host launcher — launch idx 3 (ncu capture slot) = 32-step probe scan7c.
// =====================================================================
extern "C" void kernel_launch(void* const* d_in, const int* in_sizes, int n_in,
                              void* d_out, int out_size)
{
    const float* features  = (const float*)d_in[0];
    const int*   day_idx   = (const int*)  d_in[1];
    const float* day_W     = (const float*)d_in[2];
    const float* day_b     = (const float*)d_in[3];
    const float* in_proj_W = (const float*)d_in[4];
    const float* in_proj_b = (const float*)d_in[5];
    const float* ln_w      = (const float*)d_in[6];
    const float* conv_W    = (const float*)d_in[7];
    const float* conv_b    = (const float*)d_in[8];
    const float* gate_W    = (const float*)d_in[9];
    const float* rec_W     = (const float*)d_in[10];
    const float* cell_b    = (const float*)d_in[11];
    const float* gn_w      = (const float*)d_in[12];
    const float* post_ln_w = (const float*)d_in[13];
    const float* out_W     = (const float*)d_in[14];
    const float* out_b     = (const float*)d_in[15];
    float* out = (float*)d_out;

    // 0,1: R re-layout
    transpose_Rv_kernel<<<1440, 256>>>(rec_W, 0);
    transpose_Rv_kernel<<<1440, 256>>>(rec_W, 10);
    // 2: init counters for probe
    scan_init_kernel<<<1, 32>>>();
    // 3: PROBE — 32-step scan7c (ncu capture slot; outputs overwritten later)
    scan7c_kernel<<<256, 384>>>(0, 32);
    // 4: day matmul + softsign
    gemm4<0,true><<<dim3(CIN/128, (BATCH*TLEN)/128), 256>>>(features, day_W, day_b, day_idx, 0);
    // 5: in_proj
    gemm4<1,true><<<dim3(DMODEL/128, (NROW+127)/128), 256>>>(nullptr, in_proj_W, in_proj_b, nullptr, 0);

    for (int l = 0; l < 5; l++) {
        ln_kernel  <<<NROW, 256>>>(ln_w + (size_t)l * DMODEL);
        conv_kernel<<<(BATCH*4*DMODEL)/256, 256>>>(conv_W + (size_t)l * DMODEL * 4,
                                                   conv_b + (size_t)l * DMODEL);
        gemm4<2,false><<<dim3(DHEAD/64, (NROW+127)/128, 16), 256>>>(nullptr, gate_W, cell_b, nullptr, l);
        transpose_gates_kernel<<<dim3(6, NPATCH, 16), dim3(32, 8)>>>();
        scan_init_kernel<<<1, 32>>>();
        scan7c_kernel<<<256, 384>>>(l, NPATCH);
        gn_kernel  <<<NROW, 128>>>(gn_w + (size_t)l * DMODEL);
    }

    ln_kernel<<<NROW, 256>>>(post_ln_w);
    out_kernel<<<NROW, 256>>>(out_W, out_b, out);
}

// round 17
// speedup vs baseline: 1.9472x; 1.9472x over previous
#include <cuda_runtime.h>
#include <cuda_bf16.h>
#include <math.h>
#include <stdint.h>

// ---------------- problem constants ----------------
#define NHEAD   4
#define DHEAD   192
#define DMODEL  768
#define CIN     512
#define TLEN    1024
#define BATCH   32
#define NPATCH  253
#define NROW    (BATCH*NPATCH)     // 8096
#define KIN     (14*512)           // 7168
#define EPSF    1e-5f
#define NCLS    41

// ---------------- device scratch (no allocations allowed) ----------------
__device__ float g_x1[(size_t)BATCH*TLEN*CIN];
__device__ float g_x [(size_t)NROW*DMODEL];
__device__ float g_xin[(size_t)NROW*DMODEL];
__device__ float g_xc [(size_t)NROW*DMODEL];
__device__ float g_gates[(size_t)NROW*4*DMODEL];   // [b*253+s][g][h][e]
__device__ float g_gt[(size_t)NROW*4*DMODEL];      // [s][g*4+h][e][b]
__device__ float g_y [(size_t)NROW*DMODEL];        // [s][h][e][b]
__device__ float g_Rv[(size_t)5*NHEAD*DHEAD*DHEAD*4]; // [l][h][d][e][g]
__device__ float g_h2[2][NHEAD][2][DHEAD][16];     // [buf][h][bhalf][d][b16]
__device__ unsigned g_ctr2[NHEAD*2];

// ---------------- tf32 helpers ----------------
__device__ __forceinline__ uint32_t f2tf32(float v) {
    uint32_t r;
    asm("cvt.rna.tf32.f32 %0, %1;" : "=r"(r) : "f"(v));
    return r;
}
__device__ __forceinline__ void tf32_split(float v, uint32_t& hi, uint32_t& lo) {
    hi = f2tf32(v);
    lo = f2tf32(v - __uint_as_float(hi));
}
__device__ __forceinline__ void mma_tf32(float4& d, const uint32_t a[4], const uint32_t b[2]) {
    asm volatile(
        "mma.sync.aligned.m16n8k8.row.col.f32.tf32.tf32.f32 "
        "{%0,%1,%2,%3},{%4,%5,%6,%7},{%8,%9},{%0,%1,%2,%3};"
        : "+f"(d.x), "+f"(d.y), "+f"(d.z), "+f"(d.w)
        : "r"(a[0]), "r"(a[1]), "r"(a[2]), "r"(a[3]),
          "r"(b[0]), "r"(b[1]));
}
__device__ __forceinline__ int bsw(int block) { return block ^ ((block >> 3) & 7); }

// release/acquire counter ops
__device__ __forceinline__ void red_release_add(unsigned* p, unsigned v) {
    asm volatile("red.release.gpu.global.add.u32 [%0], %1;" :: "l"(p), "r"(v) : "memory");
}
__device__ __forceinline__ unsigned ld_acquire(const unsigned* p) {
    unsigned v;
    asm volatile("ld.acquire.gpu.global.u32 %0, [%1];" : "=r"(v) : "l"(p) : "memory");
    return v;
}

// =====================================================================
// tf32 tensor-core GEMM. X3=true: tf32x3 (day/in_proj, 2 blk/SM);
// X3=false: single tf32 (gate GEMMs) — Asl elided (-8KB SMEM), 3 blk/SM.
// =====================================================================
template<int MODE, bool X3>
__global__ void __launch_bounds__(256, (MODE==2 ? 3 : 2)) gemm4(
    const float* __restrict__ Aext, const float* __restrict__ Bw,
    const float* __restrict__ bias, const int* __restrict__ day_idx, int layer)
{
    constexpr int M   = (MODE==0) ? (BATCH*TLEN) : NROW;
    constexpr int N   = (MODE==0) ? CIN : (MODE==1 ? DMODEL : DHEAD);
    constexpr int K   = (MODE==0) ? CIN : (MODE==1 ? KIN : DHEAD);
    constexpr int BN  = (MODE==2) ? 64 : 128;
    constexpr int LDC = (MODE==0) ? CIN : (MODE==1 ? DMODEL : 3072);
    constexpr int NT  = K / 8;
    constexpr int NTILE = (BN/2) / 8;
    constexpr int NTB   = BN / 8;
    constexpr int ASLN  = X3 ? (8*32*4) : 1;   // dead when !X3

    __shared__ __align__(16) uint32_t Ash[2][8*32*4];
    __shared__ __align__(16) uint32_t Asl[2][ASLN];
    __shared__ __align__(16) uint32_t Bsp[2][NTB*32*4];

    const int tid  = threadIdx.x;
    const int wid  = tid >> 5;
    const int lane = tid & 31;
    const int grp  = lane >> 2;
    const int tg   = lane & 3;

    const int rowbase = blockIdx.y * 128;
    const int colbase = blockIdx.x * BN;

    const float* bvec;
    float* Cbase;
    const float* aload;
    const float* bload;

    const int am  = tid >> 1;
    const int akq = (tid & 1) * 4;
    int mg0 = rowbase + am; if (mg0 > M - 1) mg0 = M - 1;

    if constexpr (MODE == 0) {
        const int day = day_idx[0];
        const float* Bbase = Bw + (size_t)day * K * N;
        bvec  = bias + (size_t)day * N;
        Cbase = g_x1;
        aload = Aext + (size_t)mg0 * K;
        bload = Bbase + (size_t)(tid >> 5) * N + colbase + (tid & 31) * 4;
    } else if constexpr (MODE == 1) {
        bvec  = bias;
        Cbase = g_x;
        int bb = mg0 / 253, p = mg0 - bb * 253;
        aload = g_x1 + ((size_t)bb * TLEN + (size_t)p * 4) * CIN;
        bload = Bw + (size_t)(colbase + (tid >> 1)) * KIN + (tid & 1) * 4;
    } else {
        const int z  = blockIdx.z;
        const int gg = z >> 2;
        const int hh = z & 3;
        const float* A = (gg < 2 ? g_xc : g_xin);
        const float* Bbase = Bw + (size_t)((layer*4 + gg)*4 + hh) * (192*192);
        bvec  = bias + (size_t)((layer*4 + hh)*4 + gg) * 192;
        Cbase = g_gates + (size_t)gg * 768 + (size_t)hh * 192;
        aload = A + (size_t)mg0 * DMODEL + hh * 192;
        bload = Bbase + (size_t)(tid >> 5) * 192 + colbase + (tid & 31) * 2;
    }

    float4 av, bv;
    auto fetchAB = [&](int t) {
        if constexpr (MODE == 1) {
            int kg = t*8 + akq;
            av = *reinterpret_cast<const float4*>(aload + (kg >> 9) * CIN + (kg & 511));
            bv = *reinterpret_cast<const float4*>(bload + t * 8);
        } else if constexpr (MODE == 0) {
            av = *reinterpret_cast<const float4*>(aload + t*8 + akq);
            bv = *reinterpret_cast<const float4*>(bload + (size_t)t * 8 * N);
        } else {
            av = *reinterpret_cast<const float4*>(aload + t*8 + akq);
            float2 v = *reinterpret_cast<const float2*>(bload + (size_t)t * 8 * 192);
            bv.x = v.x; bv.y = v.y; bv.z = 0.f; bv.w = 0.f;
        }
    };

    auto stage = [&](int buf) {
        {
            const float a4[4] = {av.x, av.y, av.z, av.w};
            const int mt  = am >> 4;
            const int r   = am & 15;
            const int g8  = r & 7;
            const int rhi = r >> 3;
            const int khi = akq >> 2;
            const int regj = rhi + 2*khi;
            #pragma unroll
            for (int j = 0; j < 4; j++) {
                int w = bsw(mt*32 + g8*4 + j) * 4 + regj;
                if constexpr (X3) {
                    uint32_t hi, lo; tf32_split(a4[j], hi, lo);
                    Ash[buf][w] = hi; Asl[buf][w] = lo;
                } else {
                    Ash[buf][w] = f2tf32(a4[j]);
                }
            }
        }
        if constexpr (MODE == 0) {
            const float b4[4] = {bv.x, bv.y, bv.z, bv.w};
            const int bk = tid >> 5, bn0 = (tid & 31) * 4;
            const int btg = bk & 3, bkhi = bk >> 2;
            #pragma unroll
            for (int j = 0; j < 4; j++) {
                int n = bn0 + j;
                int w = bsw((n >> 3)*32 + (n & 7)*4 + btg) * 4;
                uint32_t hi, lo; tf32_split(b4[j], hi, lo);
                Bsp[buf][w + bkhi] = hi; Bsp[buf][w + 2 + bkhi] = lo;
            }
        } else if constexpr (MODE == 1) {
            const float b4[4] = {bv.x, bv.y, bv.z, bv.w};
            const int bn = tid >> 1, bkhi = (tid & 1);
            #pragma unroll
            for (int j = 0; j < 4; j++) {
                int w = bsw((bn >> 3)*32 + (bn & 7)*4 + j) * 4;
                uint32_t hi, lo; tf32_split(b4[j], hi, lo);
                Bsp[buf][w + bkhi] = hi; Bsp[buf][w + 2 + bkhi] = lo;
            }
        } else {
            const int bk = tid >> 5, bn0 = (tid & 31) * 2;
            const int btg = bk & 3, bkhi = bk >> 2;
            const float b2[2] = {bv.x, bv.y};
            #pragma unroll
            for (int j = 0; j < 2; j++) {
                int n = bn0 + j;
                int w = bsw((n >> 3)*32 + (n & 7)*4 + btg) * 4;
                if constexpr (X3) {
                    uint32_t hi, lo; tf32_split(b2[j], hi, lo);
                    Bsp[buf][w + bkhi] = hi; Bsp[buf][w + 2 + bkhi] = lo;
                } else {
                    Bsp[buf][w + bkhi] = f2tf32(b2[j]);
                }
            }
        }
    };

    fetchAB(0);
    stage(0);
    __syncthreads();

    float4 acc[2][NTILE];
    #pragma unroll
    for (int mt = 0; mt < 2; mt++)
        #pragma unroll
        for (int nt = 0; nt < NTILE; nt++)
            acc[mt][nt] = make_float4(0.f, 0.f, 0.f, 0.f);

    for (int t = 0; t < NT; t++) {
        const int buf = t & 1;
        if (t + 1 < NT) fetchAB(t + 1);

        uint32_t ah[2][4], al[2][4];
        #pragma unroll
        for (int mtl = 0; mtl < 2; mtl++) {
            int mt = (wid & 3)*2 + mtl;
            int w = bsw(mt*32 + lane) * 4;
            *reinterpret_cast<uint4*>(ah[mtl]) = *reinterpret_cast<const uint4*>(&Ash[buf][w]);
            if constexpr (X3)
                *reinterpret_cast<uint4*>(al[mtl]) = *reinterpret_cast<const uint4*>(&Asl[buf][w]);
        }
        #pragma unroll
        for (int nt = 0; nt < NTILE; nt++) {
            int ntg = (wid >> 2)*NTILE + nt;
            uint4 bq = *reinterpret_cast<const uint4*>(&Bsp[buf][bsw(ntg*32 + lane) * 4]);
            uint32_t bh[2] = {bq.x, bq.y};
            uint32_t bl[2] = {bq.z, bq.w};
            #pragma unroll
            for (int mtl = 0; mtl < 2; mtl++) {
                if constexpr (X3) {
                    mma_tf32(acc[mtl][nt], al[mtl], bh);
                    mma_tf32(acc[mtl][nt], ah[mtl], bl);
                }
                mma_tf32(acc[mtl][nt], ah[mtl], bh);
            }
        }
        if (t + 1 < NT) { stage(buf ^ 1); __syncthreads(); }
    }

    #pragma unroll
    for (int mtl = 0; mtl < 2; mtl++) {
        int r0 = rowbase + (wid & 3)*32 + mtl*16 + grp;
        #pragma unroll
        for (int nt = 0; nt < NTILE; nt++) {
            int cc = colbase + (wid >> 2)*(BN/2) + nt*8 + tg*2;
            float2 bb = *reinterpret_cast<const float2*>(&bvec[cc]);
            if (r0 < M) {
                float2 v; v.x = acc[mtl][nt].x + bb.x; v.y = acc[mtl][nt].y + bb.y;
                if constexpr (MODE == 0) {
                    v.x = v.x/(1.f+fabsf(v.x)); v.y = v.y/(1.f+fabsf(v.y));
                }
                *reinterpret_cast<float2*>(Cbase + (size_t)r0 * LDC + cc) = v;
            }
            if (r0 + 8 < M) {
                float2 v; v.x = acc[mtl][nt].z + bb.x; v.y = acc[mtl][nt].w + bb.y;
                if constexpr (MODE == 0) {
                    v.x = v.x/(1.f+fabsf(v.x)); v.y = v.y/(1.f+fabsf(v.y));
                }
                *reinterpret_cast<float2*>(Cbase + (size_t)(r0+8) * LDC + cc) = v;
            }
        }
    }
}

// =====================================================================
// Re-layout rec_W [l][h][d][g][e] -> g_Rv [l][h][d][e][g]
// =====================================================================
__global__ void __launch_bounds__(256) transpose_Rv_kernel(
    const float* __restrict__ R, int lh0)
{
    int idx = blockIdx.x * 256 + threadIdx.x;
    int e = idx % 192;
    int t = idx / 192;
    int d = t % 192;
    int lh = lh0 + t / 192;
    const float* src = R + ((size_t)(lh*192 + d) * 4) * 192 + e;
    float4 v;
    v.x = src[0]; v.y = src[192]; v.z = src[384]; v.w = src[576];
    *reinterpret_cast<float4*>(g_Rv + ((size_t)(lh*192 + d) * 192 + e) * 4) = v;
}

// =====================================================================
// Transpose gates [b*253+s][g][h][e] -> g_gt [s][g*4+h][e][b]
// =====================================================================
__global__ void __launch_bounds__(256) transpose_gates_kernel()
{
    __shared__ float t[32][33];
    const int e0 = blockIdx.x * 32;
    const int s  = blockIdx.y;
    const int gh = blockIdx.z;          // g*4+h
    const int tx = threadIdx.x, ty = threadIdx.y;
    #pragma unroll
    for (int k = 0; k < 4; k++) {
        int b = ty + 8*k;
        t[b][tx] = g_gates[(size_t)(b*NPATCH + s) * 3072 + gh*192 + e0 + tx];
    }
    __syncthreads();
    #pragma unroll
    for (int k = 0; k < 4; k++) {
        int e = ty + 8*k;
        g_gt[((size_t)(s*16 + gh)*192 + e0 + e)*32 + tx] = t[tx][e];
    }
}

// =====================================================================
// scan init: zero 8 barrier counters
// =====================================================================
__global__ void scan_init_kernel()
{
    if (threadIdx.x < NHEAD*2) g_ctr2[threadIdx.x] = 0u;
}

// =====================================================================
// sLSTM scan v7b (PROVEN 8087us config — tid0 poll + BAR wait):
// 256 blocks = 4h x 2bh x 32 e-slices(6e); 384 threads = 3 epair x 4 dh x 32.
// =====================================================================
__global__ void __launch_bounds__(384) scan7b_kernel(int layer, int nsteps)
{
    const int h  = blockIdx.x >> 6;
    const int bh = (blockIdx.x >> 5) & 1;
    const int j  = blockIdx.x & 31;
    const int e0 = j * 6;
    const int tid  = threadIdx.x;
    const int lane = tid & 31;
    const int w    = tid >> 5;          // 0..11
    const int epair = w >> 2;           // 0..2
    const int dh    = w & 3;            // 0..3
    const int eh    = lane >> 4;        // 0..1
    const int b     = lane & 15;        // 0..15
    const int eloc  = epair*2 + eh;     // 0..5
    const int e     = e0 + eloc;
    const int b32   = bh*16 + b;
    unsigned* ctr = &g_ctr2[h*2 + bh];

    __shared__ float4 Rs[192][6];       // 18.4 KB
    __shared__ float  hsm[192*16];      // 12 KB
    __shared__ float4 part[3][6][16];   // 4.6 KB

    // load R slice once
    {
        const float4* src = reinterpret_cast<const float4*>(g_Rv)
                          + (size_t)(layer*4 + h) * 192 * 192;
        for (int i = tid; i < 192*6; i += 384) {
            int d = i / 6, el = i - d*6;
            Rs[d][el] = src[(size_t)d * 192 + e0 + el];
        }
    }
    float c = 0.f, n = 0.f, m = 0.f;
    const float* gtb = g_gt + ((size_t)h*192 + e)*32 + b32;   // + s*98304, g*24576
    float* ytb = g_y + ((size_t)h*192 + e)*32 + b32;          // + s*24576

    float pgi = 0.f, pgf = 0.f, pgz = 0.f, pgo = 0.f;
    if (dh == 0) {
        pgi = __ldg(gtb);
        pgf = __ldg(gtb + 24576);
        pgz = __ldg(gtb + 49152);
        pgo = __ldg(gtb + 73728);
    }
    __syncthreads();

    for (int s = 0; s < nsteps; s++) {
        const int p = s & 1;
        float a0=0.f, a1=0.f, a2=0.f, a3=0.f;
        if (s > 0) {
            // stage this half's h slab (192 d x 16 b) into smem
            const float4* hp = reinterpret_cast<const float4*>(&g_h2[p][h][bh][0][0]);
            #pragma unroll
            for (int i = 0; i < 2; i++) {
                int idx = tid + i * 384;            // 0..767
                float4 v = __ldcg(hp + idx);
                *reinterpret_cast<float4*>(&hsm[idx * 4]) = v;
            }
            __syncthreads();

            const int d0 = dh * 48;
            #pragma unroll 4
            for (int d = d0; d < d0 + 48; d++) {
                float hv = hsm[d*16 + b];
                float4 r = Rs[d][eloc];
                a0 = fmaf(hv, r.x, a0);
                a1 = fmaf(hv, r.y, a1);
                a2 = fmaf(hv, r.z, a2);
                a3 = fmaf(hv, r.w, a3);
            }
        }
        if (dh > 0) part[dh-1][eloc][b] = make_float4(a0, a1, a2, a3);
        __syncthreads();

        float y = 0.f;
        if (dh == 0) {
            #pragma unroll
            for (int k = 0; k < 3; k++) {
                float4 q = part[k][eloc][b];
                a0 += q.x; a1 += q.y; a2 += q.z; a3 += q.w;
            }
            float iraw = a0 + pgi;
            float fraw = a1 + pgf;
            float zraw = a2 + pgz;
            float oraw = a3 + pgo;
            float lsf  = fminf(fraw, 0.f) - __logf(1.f + __expf(-fabsf(fraw)));
            float lfm  = m + lsf;
            float mnew = (s == 0) ? iraw : fmaxf(iraw, lfm);
            float ig = __expf(iraw - mnew), fg = __expf(lfm - mnew);
            float t2 = __expf(-2.f * fabsf(zraw));
            float th = copysignf(__fdividef(1.f - t2, 1.f + t2), zraw);
            float cnew = fg * c + ig * th;
            float nnew = fg * n + ig;
            float sg = __fdividef(1.f, 1.f + __expf(-oraw));
            y  = __fdividef(cnew, nnew) * sg;
            c = cnew; n = nnew; m = mnew;
            if (s + 1 < nsteps) g_h2[p ^ 1][h][bh][e][b] = y;
        }

        if (s + 1 < nsteps) {
            __syncthreads();                        // h stores done block-wide
            if (tid == 0) red_release_add(ctr, 1u); // release early
            if (dh == 0) {                          // overlap with spin window
                ytb[(size_t)s * 24576] = y;
                const float* gp = gtb + (size_t)(s + 1) * 98304;
                pgi = __ldg(gp);
                pgf = __ldg(gp + 24576);
                pgz = __ldg(gp + 49152);
                pgo = __ldg(gp + 73728);
            }
            if (tid == 0) {
                unsigned tgt = 32u * (unsigned)(s + 1);
                while (ld_acquire(ctr) < tgt) { }
            }
            __syncthreads();
        } else {
            if (dh == 0) ytb[(size_t)s * 24576] = y;
        }
    }
}

// =====================================================================
// LayerNorm (weight only): g_x -> g_xin.
// =====================================================================
__global__ void __launch_bounds__(256) ln_kernel(const float* __restrict__ w)
{
    __shared__ float sbuf[16];
    const int row = blockIdx.x;
    const int tid = threadIdx.x;
    const float* xp = g_x + (size_t)row * DMODEL;
    float v0 = xp[tid], v1 = xp[tid+256], v2 = xp[tid+512];
    float s  = v0 + v1 + v2;
    float ss = v0*v0 + v1*v1 + v2*v2;
    const unsigned full = 0xffffffffu;
    #pragma unroll
    for (int o = 16; o > 0; o >>= 1) {
        s  += __shfl_down_sync(full, s, o);
        ss += __shfl_down_sync(full, ss, o);
    }
    int wp = tid >> 5;
    if ((tid & 31) == 0) { sbuf[wp] = s; sbuf[wp+8] = ss; }
    __syncthreads();
    if (tid == 0) {
        float sa = 0.f, sb = 0.f;
        #pragma unroll
        for (int i = 0; i < 8; i++) { sa += sbuf[i]; sb += sbuf[i+8]; }
        sbuf[0] = sa; sbuf[8] = sb;
    }
    __syncthreads();
    float mu  = sbuf[0] * (1.f/768.f);
    float var = sbuf[8] * (1.f/768.f) - mu*mu;
    float rs  = rsqrtf(var + EPSF);
    float* op = g_xin + (size_t)row * DMODEL;
    op[tid]     = (v0 - mu) * rs * w[tid];
    op[tid+256] = (v1 - mu) * rs * w[tid+256];
    op[tid+512] = (v2 - mu) * rs * w[tid+512];
}

// =====================================================================
// Causal depthwise conv (k=4) + SiLU, chunked over time.
// =====================================================================
__global__ void __launch_bounds__(256) conv_kernel(
    const float* __restrict__ Wc, const float* __restrict__ cb)
{
    const int gid = blockIdx.x * 256 + threadIdx.x;
    const int d  = gid % DMODEL;
    const int r  = gid / DMODEL;
    const int ch = r & 3;
    const int b  = r >> 2;
    const int p0 = ch * 64;
    const int p1 = (p0 + 64 < NPATCH) ? p0 + 64 : NPATCH;
    const float w0 = Wc[d*4+0], w1 = Wc[d*4+1], w2 = Wc[d*4+2], w3 = Wc[d*4+3];
    const float bias = cb[d];
    const float* src = g_xin + (size_t)b * NPATCH * DMODEL + d;
    float*       dst = g_xc  + (size_t)b * NPATCH * DMODEL + d;
    float h0 = (p0 >= 3) ? src[(size_t)(p0-3)*DMODEL] : 0.f;
    float h1 = (p0 >= 2) ? src[(size_t)(p0-2)*DMODEL] : 0.f;
    float h2 = (p0 >= 1) ? src[(size_t)(p0-1)*DMODEL] : 0.f;
    for (int p = p0; p < p1; p++) {
        float v = src[(size_t)p * DMODEL];
        float o = fmaf(w0,h0, fmaf(w1,h1, fmaf(w2,h2, fmaf(w3,v, bias))));
        dst[(size_t)p * DMODEL] = o / (1.f + expf(-o));
        h0 = h1; h1 = h2; h2 = v;
    }
}

// =====================================================================
// GroupNorm + residual add into g_x (reads y from [s][h][e][b]).
// =====================================================================
__global__ void __launch_bounds__(128) gn_kernel(const float* __restrict__ gw)
{
    const int row  = blockIdx.x;          // m = b*253+s
    const int bb   = row / NPATCH;
    const int s    = row - bb * NPATCH;
    const int wp   = threadIdx.x >> 5;    // head
    const int lane = threadIdx.x & 31;
    const float* yb = g_y + ((size_t)(s*4 + wp) * 192) * 32 + bb;
    float v[6]; float sm = 0.f, ss = 0.f;
    #pragma unroll
    for (int j = 0; j < 6; j++) {
        v[j] = __ldg(yb + (size_t)(lane + 32*j) * 32);
        sm += v[j]; ss += v[j]*v[j];
    }
    const unsigned full = 0xffffffffu;
    #pragma unroll
    for (int o = 16; o > 0; o >>= 1) {
        sm += __shfl_xor_sync(full, sm, o);
        ss += __shfl_xor_sync(full, ss, o);
    }
    float mu  = sm * (1.f/192.f);
    float var = ss * (1.f/192.f) - mu*mu;
    float rs  = rsqrtf(var + EPSF);
    float* xp = g_x + (size_t)row * DMODEL + wp * 192;
    const float* gwp = gw + wp * 192;
    #pragma unroll
    for (int j = 0; j < 6; j++) {
        int i = lane + 32*j;
        xp[i] += (v[j] - mu) * rs * gwp[i];
    }
}

// =====================================================================
// Classifier — coalesced float4 W loads + shfl reduction.
// =====================================================================
__global__ void __launch_bounds__(256) out_kernel(
    const float* __restrict__ W, const float* __restrict__ bias,
    float* __restrict__ out)
{
    __shared__ float4 xs[192];
    const int row  = blockIdx.x;
    const int tid  = threadIdx.x;
    const int lane = tid & 31;
    const int wid  = tid >> 5;
    const float4* xp = reinterpret_cast<const float4*>(g_xin + (size_t)row * DMODEL);
    if (tid < 192) xs[tid] = xp[tid];
    __syncthreads();
    for (int cc = wid; cc < NCLS; cc += 8) {
        const float4* wr = reinterpret_cast<const float4*>(W + (size_t)cc * DMODEL);
        float acc = 0.f;
        #pragma unroll
        for (int i = 0; i < 6; i++) {
            float4 w4 = wr[lane + 32*i];
            float4 x4 = xs[lane + 32*i];
            acc += w4.x*x4.x + w4.y*x4.y + w4.z*x4.z + w4.w*x4.w;
        }
        #pragma unroll
        for (int o = 16; o > 0; o >>= 1)
            acc += __shfl_down_sync(0xffffffffu, acc, o);
        if (lane == 0) out[(size_t)row * NCLS + cc] = acc + bias[cc];
    }
}

// =====================================================================
// Host launcher — launch idx 3 (ncu capture slot) = gate-GEMM probe
// (now 3 blk/SM; reads stale xc/xin, output overwritten before use).
// =====================================================================
extern "C" void kernel_launch(void* const* d_in, const int* in_sizes, int n_in,
                              void* d_out, int out_size)
{
    const float* features  = (const float*)d_in[0];
    const int*   day_idx   = (const int*)  d_in[1];
    const float* day_W     = (const float*)d_in[2];
    const float* day_b     = (const float*)d_in[3];
    const float* in_proj_W = (const float*)d_in[4];
    const float* in_proj_b = (const float*)d_in[5];
    const float* ln_w      = (const float*)d_in[6];
    const float* conv_W    = (const float*)d_in[7];
    const float* conv_b    = (const float*)d_in[8];
    const float* gate_W    = (const float*)d_in[9];
    const float* rec_W     = (const float*)d_in[10];
    const float* cell_b    = (const float*)d_in[11];
    const float* gn_w      = (const float*)d_in[12];
    const float* post_ln_w = (const float*)d_in[13];
    const float* out_W     = (const float*)d_in[14];
    const float* out_b     = (const float*)d_in[15];
    float* out = (float*)d_out;

    // 0,1: R re-layout
    transpose_Rv_kernel<<<1440, 256>>>(rec_W, 0);
    transpose_Rv_kernel<<<1440, 256>>>(rec_W, 10);
    // 2: day matmul + softsign
    gemm4<0,true><<<dim3(CIN/128, (BATCH*TLEN)/128), 256>>>(features, day_W, day_b, day_idx, 0);
    // 3: PROBE — gate GEMM with new occupancy config (ncu capture slot)
    gemm4<2,false><<<dim3(DHEAD/64, (NROW+127)/128, 16), 256>>>(nullptr, gate_W, cell_b, nullptr, 0);
    // 4: in_proj
    gemm4<1,true><<<dim3(DMODEL/128, (NROW+127)/128), 256>>>(nullptr, in_proj_W, in_proj_b, nullptr, 0);

    for (int l = 0; l < 5; l++) {
        ln_kernel  <<<NROW, 256>>>(ln_w + (size_t)l * DMODEL);
        conv_kernel<<<(BATCH*4*DMODEL)/256, 256>>>(conv_W + (size_t)l * DMODEL * 4,
                                                   conv_b + (size_t)l * DMODEL);
        gemm4<2,false><<<dim3(DHEAD/64, (NROW+127)/128, 16), 256>>>(nullptr, gate_W, cell_b, nullptr, l);
        transpose_gates_kernel<<<dim3(6, NPATCH, 16), dim3(32, 8)>>>();
        scan_init_kernel<<<1, 32>>>();
        scan7b_kernel<<<256, 384>>>(l, NPATCH);
        gn_kernel  <<<NROW, 128>>>(gn_w + (size_t)l * DMODEL);
    }

    ln_kernel<<<NROW, 256>>>(post_ln_w);
    out_kernel<<<NROW, 256>>>(out_W, out_b, out);
}